// round 15
// baseline (speedup 1.0000x reference)
#include <cuda_runtime.h>
#include <math.h>
#include <stdint.h>

#define Bn 4
#define Tn 2048
#define Cn 1024
#define Hn 16
#define Dn 64
#define NT (Bn * Tn)
#define C3 (3 * Cn)

__device__ float g_q[(size_t)Bn * Hn * Tn * Dn];
__device__ float g_k[(size_t)Bn * Hn * Tn * Dn];   // tf32-rounded by producer
__device__ float g_v[(size_t)Bn * Hn * Tn * Dn];   // tf32-rounded by producer
__device__ float g_y[(size_t)NT * Cn];             // tf32-rounded by producer
__device__ float g_x[(size_t)NT * Cn];             // tf32-rounded x
__device__ float g_wqkv[(size_t)Cn * C3];          // tf32-rounded w_qkv
__device__ float g_wproj[(size_t)Cn * Cn];         // tf32-rounded w_proj

// ---------------------------------------------------------------------------
// helpers
// ---------------------------------------------------------------------------
__device__ __forceinline__ float f2tf(float x) {
    float y;
    asm("cvt.rna.tf32.f32 %0, %1;" : "=f"(y) : "f"(x));
    return y;
}
__device__ __forceinline__ float ex2(float x) {
    float y;
    asm("ex2.approx.f32 %0, %1;" : "=f"(y) : "f"(x));
    return y;
}
__device__ __forceinline__ void mma8(float d[4], const uint32_t a[4],
                                     const uint32_t b[2], const float c[4]) {
    asm volatile(
        "mma.sync.aligned.m16n8k8.row.col.f32.tf32.tf32.f32 "
        "{%0,%1,%2,%3}, {%4,%5,%6,%7}, {%8,%9}, {%10,%11,%12,%13};"
        : "=f"(d[0]), "=f"(d[1]), "=f"(d[2]), "=f"(d[3])
        : "r"(a[0]), "r"(a[1]), "r"(a[2]), "r"(a[3]),
          "r"(b[0]), "r"(b[1]),
          "f"(c[0]), "f"(c[1]), "f"(c[2]), "f"(c[3]));
}
__device__ __forceinline__ uint32_t smem_u32(const void* p) {
    return (uint32_t)__cvta_generic_to_shared(p);
}

#define CPA16(s, gp) \
    asm volatile("cp.async.cg.shared.global [%0], [%1], 16;" :: "r"(s), "l"(gp))

// ---------------------------------------------------------------------------
// Prepass: RNA-round fp32 -> tf32-in-fp32 into device globals.
// ---------------------------------------------------------------------------
template <int WHICH>
__global__ void round_tf32(const float* __restrict__ src, int n4) {
    float* dst = (WHICH == 0) ? g_x : (WHICH == 1) ? g_wqkv : g_wproj;
    const int i = blockIdx.x * blockDim.x + threadIdx.x;
    if (i < n4) {
        float4 v = ((const float4*)src)[i];
        ((float4*)dst)[i] =
            make_float4(f2tf(v.x), f2tf(v.y), f2tf(v.z), f2tf(v.w));
    }
}

// ---------------------------------------------------------------------------
// GEMM v4 = R9 geometry with BK=32 (half the barriers: 32 iters, 4 ks-steps
// per buffer). Smem: As [2][128][36] (stride 36 ≡ 4 mod 32, conflict-free),
// Bs [2][32][136]. 71.7 KB/CTA -> still 2 CTAs/SM. Accumulation k-order is
// unchanged (ascending) -> bit-identical results vs BK=16.
// MODE 0 epilogue writes f2tf-rounded K/V (producer-side rounding).
// ---------------------------------------------------------------------------
#define GEMM_SMEM ((2 * 128 * 36 + 2 * 32 * 136) * 4)

template <int MODE>
__global__ __launch_bounds__(256, 2) void gemm_v4(const float* __restrict__ bias,
                                                  float* __restrict__ out) {
    const float* __restrict__ A = MODE ? (const float*)g_y : (const float*)g_x;
    const float* __restrict__ W = MODE ? (const float*)g_wproj : (const float*)g_wqkv;
    const int ldb = MODE ? Cn : C3;

    extern __shared__ float sm[];
    float* Asm = sm;                 // [2][128][36]
    float* Bsm = sm + 2 * 128 * 36;  // [2][32][136]

    const int tid = threadIdx.x;
    const int lane = tid & 31;
    const int warp = tid >> 5;
    const int warpM = warp & 3;
    const int warpN = warp >> 2;
    const int g = lane >> 2;
    const int q = lane & 3;

    const int rowBase = blockIdx.y * 128;
    const int colBase = blockIdx.x * 128;

    // A loader: row tid>>1 (0..127), 16-float half (tid&1)*16
    const int aRow = tid >> 1;
    const int aOff = (tid & 1) * 16;
    // B loader: row tid>>3 (0..31), 16-float chunk (tid&7)*16
    const int bRow = tid >> 3;
    const int bCol = (tid & 7) * 16;

    const float* agp = A + (size_t)(rowBase + aRow) * Cn + aOff;
    const float* bgp = W + (size_t)bRow * ldb + colBase + bCol;

    const uint32_t asBase = smem_u32(&Asm[aRow * 36 + aOff]);
    const uint32_t bsBase = smem_u32(&Bsm[bRow * 136 + bCol]);

    float acc[2][8][4] = {};

#define ISSUE_TILE(k0, buf)                                       \
    do {                                                          \
        const float* ag = agp + (k0);                             \
        const uint32_t as = asBase + (buf) * (4608 * 4);          \
        CPA16(as,      ag);                                       \
        CPA16(as + 16, ag + 4);                                   \
        CPA16(as + 32, ag + 8);                                   \
        CPA16(as + 48, ag + 12);                                  \
        const float* bg = bgp + (size_t)(k0) * ldb;               \
        const uint32_t bs = bsBase + (buf) * (4352 * 4);          \
        CPA16(bs,      bg);                                       \
        CPA16(bs + 16, bg + 4);                                   \
        CPA16(bs + 32, bg + 8);                                   \
        CPA16(bs + 48, bg + 12);                                  \
        asm volatile("cp.async.commit_group;");                   \
    } while (0)

    ISSUE_TILE(0, 0);

    for (int it = 0; it < 32; it++) {
        const int buf = it & 1;
        if (it < 31) {
            ISSUE_TILE((it + 1) * 32, buf ^ 1);
            asm volatile("cp.async.wait_group 1;");
        } else {
            asm volatile("cp.async.wait_group 0;");
        }
        __syncthreads();

        const float* Ab = &Asm[buf * 4608];
        const float* Bb = &Bsm[buf * 4352];
#pragma unroll
        for (int ks = 0; ks < 32; ks += 8) {
            uint32_t afr[2][4];
#pragma unroll
            for (int mt = 0; mt < 2; mt++) {
                const int r = warpM * 32 + mt * 16 + g;
                afr[mt][0] = __float_as_uint(Ab[r * 36 + ks + q]);
                afr[mt][1] = __float_as_uint(Ab[(r + 8) * 36 + ks + q]);
                afr[mt][2] = __float_as_uint(Ab[r * 36 + ks + q + 4]);
                afr[mt][3] = __float_as_uint(Ab[(r + 8) * 36 + ks + q + 4]);
            }
#pragma unroll
            for (int nt = 0; nt < 8; nt++) {
                const int c = warpN * 64 + nt * 8 + g;
                uint32_t b2[2];
                b2[0] = __float_as_uint(Bb[(ks + q) * 136 + c]);
                b2[1] = __float_as_uint(Bb[(ks + q + 4) * 136 + c]);
#pragma unroll
                for (int mt = 0; mt < 2; mt++)
                    mma8(acc[mt][nt], afr[mt], b2, acc[mt][nt]);
            }
        }
        __syncthreads();
    }

#pragma unroll
    for (int mt = 0; mt < 2; mt++) {
#pragma unroll
        for (int ih = 0; ih < 2; ih++) {
            const int m = rowBase + warpM * 32 + mt * 16 + g + ih * 8;
#pragma unroll
            for (int nt = 0; nt < 8; nt++) {
                const int n = colBase + warpN * 64 + nt * 8 + q * 2;
                const float v0 = acc[mt][nt][ih * 2 + 0] + bias[n];
                const float v1 = acc[mt][nt][ih * 2 + 1] + bias[n + 1];
                if (MODE == 1) {
                    *(float2*)&out[(size_t)m * Cn + n] = make_float2(v0, v1);
                } else {
                    const int which = n >> 10;       // 0=q 1=k 2=v
                    const int cc = n & 1023;
                    const int h = cc >> 6;
                    const int d = cc & 63;
                    const int b = m >> 11;
                    const int t = m & 2047;
                    float* dst = (which == 0) ? g_q : (which == 1) ? g_k : g_v;
                    const float s0 = (which == 0) ? v0 : f2tf(v0);
                    const float s1 = (which == 0) ? v1 : f2tf(v1);
                    *(float2*)&dst[(((size_t)b * Hn + h) * Tn + t) * Dn + d] =
                        make_float2(s0, s1);
                }
            }
        }
    }
#undef ISSUE_TILE
}

// ---------------------------------------------------------------------------
// Attention v4: R9 geometry (Br=64, 4 warps, occ 3, single K/V buffer 54 KB)
// + register-staged prefetch of the next K/V tile. Same 2 barriers/iter.
// Iter j: LDG K(j+1)->regs | S=Q@K(j) | bar | STS K, LDG V(j+1)->regs |
//         softmax,P,PV(V(j)) | bar | STS V.
// K/V arrive pre-rounded (producer-side f2tf) -> loader is a raw copy.
// ---------------------------------------------------------------------------
#define LKV 72
#define ATTN_SMEM ((2 * 64 * LKV + 4 * 16 * LKV) * 4)

__global__ __launch_bounds__(128, 3) void attn_tc4() {
    extern __shared__ float smf[];
    float* Kn = smf;                    // [kv][d]  stride LKV
    float* Vs = smf + 64 * LKV;         // [kv][d]  stride LKV
    float* Pw = smf + 2 * 64 * LKV;     // per-warp [16][LKV]

    const int qt = blockIdx.x;
    const int bh = blockIdx.y;
    const int b = bh >> 4;
    const int h = bh & 15;

    const int tid = threadIdx.x;
    const int w = tid >> 5;
    const int lane = tid & 31;
    const int g = lane >> 2;
    const int q = lane & 3;

    // per-thread loader coords: 8 slices, rows r0l+8*ii, fixed 16B column
    const int r0l = tid >> 4;           // 0..7
    const int c0l = (tid & 15) * 4;     // 0..60

    const float qscale = 0.125f * 1.44269504f;
    const float* qg = g_q + ((size_t)bh * Tn + qt * 64 + w * 16) * Dn;
    uint32_t aQ[8][4];
#pragma unroll
    for (int ks = 0; ks < 8; ks++) {
        aQ[ks][0] = __float_as_uint(f2tf(qg[g * Dn + ks * 8 + q] * qscale));
        aQ[ks][1] = __float_as_uint(f2tf(qg[(g + 8) * Dn + ks * 8 + q] * qscale));
        aQ[ks][2] = __float_as_uint(f2tf(qg[g * Dn + ks * 8 + q + 4] * qscale));
        aQ[ks][3] = __float_as_uint(f2tf(qg[(g + 8) * Dn + ks * 8 + q + 4] * qscale));
    }

    float o[8][4] = {};
    float mrow[2] = {-INFINITY, -INFINITY};
    float lrow[2] = {0.0f, 0.0f};

    const float* kg0 = g_k + (size_t)bh * Tn * Dn;
    const float* vg0 = g_v + (size_t)bh * Tn * Dn;
    float* Pme = Pw + w * 16 * LKV;

    // Tile 0 straight to smem (values pre-rounded by producer)
#pragma unroll
    for (int ii = 0; ii < 8; ii++) {
        const int r = r0l + 8 * ii;
        *(float4*)&Kn[r * LKV + c0l] = *(const float4*)&kg0[r * Dn + c0l];
        *(float4*)&Vs[r * LKV + c0l] = *(const float4*)&vg0[r * Dn + c0l];
    }
    __syncthreads();

    for (int j = 0; j <= qt; j++) {
        // Prefetch K(j+1) into registers (LDGs overlap the S-GEMM below)
        float4 kreg[8];
        if (j < qt) {
            const float* kg = kg0 + (size_t)(j + 1) * 64 * Dn;
#pragma unroll
            for (int ii = 0; ii < 8; ii++)
                kreg[ii] = *(const float4*)&kg[(r0l + 8 * ii) * Dn + c0l];
        }

        // S = Q @ K(j)^T
        float s[8][4] = {};
#pragma unroll
        for (int ks = 0; ks < 8; ks++) {
            uint32_t bf[8][2];
#pragma unroll
            for (int nt = 0; nt < 8; nt++) {
                bf[nt][0] = __float_as_uint(Kn[(nt * 8 + g) * LKV + ks * 8 + q]);
                bf[nt][1] = __float_as_uint(Kn[(nt * 8 + g) * LKV + ks * 8 + q + 4]);
            }
#pragma unroll
            for (int nt = 0; nt < 8; nt++)
                mma8(s[nt], aQ[ks], bf[nt], s[nt]);
        }

        // Causal mask on the diagonal tile
        if (j == qt) {
            const int lr0 = w * 16 + g;
            const int lr1 = lr0 + 8;
#pragma unroll
            for (int nt = 0; nt < 8; nt++) {
                const int lc = nt * 8 + 2 * q;
                if (lc > lr0) s[nt][0] = -INFINITY;
                if (lc + 1 > lr0) s[nt][1] = -INFINITY;
                if (lc > lr1) s[nt][2] = -INFINITY;
                if (lc + 1 > lr1) s[nt][3] = -INFINITY;
            }
        }

        __syncthreads();   // all warps done reading Kn(j)

        // Commit K(j+1) to smem; prefetch V(j+1) into registers
        float4 vreg[8];
        if (j < qt) {
#pragma unroll
            for (int ii = 0; ii < 8; ii++)
                *(float4*)&Kn[(r0l + 8 * ii) * LKV + c0l] = kreg[ii];
            const float* vg = vg0 + (size_t)(j + 1) * 64 * Dn;
#pragma unroll
            for (int ii = 0; ii < 8; ii++)
                vreg[ii] = *(const float4*)&vg[(r0l + 8 * ii) * Dn + c0l];
        }

        // Online softmax in registers (quad shuffles); logits log2-scaled
#pragma unroll
        for (int r = 0; r < 2; r++) {
            float mx = mrow[r];
#pragma unroll
            for (int nt = 0; nt < 8; nt++)
                mx = fmaxf(mx, fmaxf(s[nt][2 * r], s[nt][2 * r + 1]));
            mx = fmaxf(mx, __shfl_xor_sync(0xffffffffu, mx, 1));
            mx = fmaxf(mx, __shfl_xor_sync(0xffffffffu, mx, 2));
            const float alpha = ex2(mrow[r] - mx);
            float sum = 0.0f;
#pragma unroll
            for (int nt = 0; nt < 8; nt++) {
                const float p0 = ex2(s[nt][2 * r] - mx);
                const float p1 = ex2(s[nt][2 * r + 1] - mx);
                s[nt][2 * r] = p0;
                s[nt][2 * r + 1] = p1;
                sum += p0 + p1;
                o[nt][2 * r] *= alpha;
                o[nt][2 * r + 1] *= alpha;
            }
            sum += __shfl_xor_sync(0xffffffffu, sum, 1);
            sum += __shfl_xor_sync(0xffffffffu, sum, 2);
            lrow[r] = lrow[r] * alpha + sum;
            mrow[r] = mx;
        }

        // P: C-layout -> per-warp smem patch -> A-layout
#pragma unroll
        for (int nt = 0; nt < 8; nt++) {
            *(float2*)&Pme[g * LKV + nt * 8 + 2 * q] =
                make_float2(f2tf(s[nt][0]), f2tf(s[nt][1]));
            *(float2*)&Pme[(g + 8) * LKV + nt * 8 + 2 * q] =
                make_float2(f2tf(s[nt][2]), f2tf(s[nt][3]));
        }
        __syncwarp();

        // O += P @ V(j)
#pragma unroll
        for (int ks = 0; ks < 8; ks++) {
            uint32_t aP[4];
            aP[0] = __float_as_uint(Pme[g * LKV + ks * 8 + q]);
            aP[1] = __float_as_uint(Pme[(g + 8) * LKV + ks * 8 + q]);
            aP[2] = __float_as_uint(Pme[g * LKV + ks * 8 + q + 4]);
            aP[3] = __float_as_uint(Pme[(g + 8) * LKV + ks * 8 + q + 4]);
            uint32_t bf[8][2];
#pragma unroll
            for (int nt = 0; nt < 8; nt++) {
                bf[nt][0] = __float_as_uint(Vs[(ks * 8 + q) * LKV + nt * 8 + g]);
                bf[nt][1] = __float_as_uint(Vs[(ks * 8 + q + 4) * LKV + nt * 8 + g]);
            }
#pragma unroll
            for (int nt = 0; nt < 8; nt++)
                mma8(o[nt], aP, bf[nt], o[nt]);
        }
        __syncthreads();   // all warps done reading Vs(j)

        if (j < qt) {
#pragma unroll
            for (int ii = 0; ii < 8; ii++)
                *(float4*)&Vs[(r0l + 8 * ii) * LKV + c0l] = vreg[ii];
        }
    }

    // Normalize + write g_y (pre-rounded for proj's raw cp.async)
    const float inv0 = 1.0f / lrow[0];
    const float inv1 = 1.0f / lrow[1];
    float* yg = g_y + ((size_t)b * Tn + qt * 64 + w * 16) * Cn + h * Dn;
#pragma unroll
    for (int nt = 0; nt < 8; nt++) {
        *(float2*)&yg[(size_t)g * Cn + nt * 8 + 2 * q] =
            make_float2(f2tf(o[nt][0] * inv0), f2tf(o[nt][1] * inv0));
        *(float2*)&yg[(size_t)(g + 8) * Cn + nt * 8 + 2 * q] =
            make_float2(f2tf(o[nt][2] * inv1), f2tf(o[nt][3] * inv1));
    }
}

// ---------------------------------------------------------------------------
extern "C" void kernel_launch(void* const* d_in, const int* in_sizes, int n_in,
                              void* d_out, int out_size) {
    const float* x      = (const float*)d_in[0];
    const float* w_qkv  = (const float*)d_in[1];
    const float* b_qkv  = (const float*)d_in[2];
    const float* w_proj = (const float*)d_in[3];
    const float* b_proj = (const float*)d_in[4];
    float* out = (float*)d_out;

    cudaFuncSetAttribute(attn_tc4,
                         cudaFuncAttributeMaxDynamicSharedMemorySize, ATTN_SMEM);
    cudaFuncSetAttribute(gemm_v4<0>,
                         cudaFuncAttributeMaxDynamicSharedMemorySize, GEMM_SMEM);
    cudaFuncSetAttribute(gemm_v4<1>,
                         cudaFuncAttributeMaxDynamicSharedMemorySize, GEMM_SMEM);

    const int nx4 = NT * Cn / 4;
    const int nw4 = Cn * C3 / 4;
    const int np4 = Cn * Cn / 4;
    round_tf32<0><<<(nx4 + 255) / 256, 256>>>(x, nx4);
    round_tf32<1><<<(nw4 + 255) / 256, 256>>>(w_qkv, nw4);
    round_tf32<2><<<(np4 + 255) / 256, 256>>>(w_proj, np4);

    gemm_v4<0><<<dim3(C3 / 128, NT / 128), 256, GEMM_SMEM>>>(b_qkv, nullptr);
    attn_tc4<<<dim3(Tn / 64, Bn * Hn), 128, ATTN_SMEM>>>();
    gemm_v4<1><<<dim3(Cn / 128, NT / 128), 256, GEMM_SMEM>>>(b_proj, out);
}

// round 17
// speedup vs baseline: 1.5249x; 1.5249x over previous
#include <cuda_runtime.h>
#include <cuda_fp16.h>
#include <math.h>
#include <stdint.h>

#define Bn 4
#define Tn 2048
#define Cn 1024
#define Hn 16
#define Dn 64
#define NT (Bn * Tn)
#define C3 (3 * Cn)

__device__ float g_q[(size_t)Bn * Hn * Tn * Dn];
__device__ float g_k[(size_t)Bn * Hn * Tn * Dn];
__device__ float g_v[(size_t)Bn * Hn * Tn * Dn];
__device__ __half g_yh[(size_t)NT * Cn];        // attention out (proj A operand)
__device__ __half g_xh[(size_t)NT * Cn];        // x as fp16
__device__ __half g_wqkvT[(size_t)C3 * Cn];     // w_qkv^T [N][K] fp16
__device__ __half g_wprojT[(size_t)Cn * Cn];    // w_proj^T [N][K] fp16

// ---------------------------------------------------------------------------
// helpers
// ---------------------------------------------------------------------------
__device__ __forceinline__ float f2tf(float x) {
    float y;
    asm("cvt.rna.tf32.f32 %0, %1;" : "=f"(y) : "f"(x));
    return y;
}
__device__ __forceinline__ float ex2(float x) {
    float y;
    asm("ex2.approx.f32 %0, %1;" : "=f"(y) : "f"(x));
    return y;
}
// tf32 m16n8k8 (attention only)
__device__ __forceinline__ void mma8(float d[4], const uint32_t a[4],
                                     const uint32_t b[2], const float c[4]) {
    asm volatile(
        "mma.sync.aligned.m16n8k8.row.col.f32.tf32.tf32.f32 "
        "{%0,%1,%2,%3}, {%4,%5,%6,%7}, {%8,%9}, {%10,%11,%12,%13};"
        : "=f"(d[0]), "=f"(d[1]), "=f"(d[2]), "=f"(d[3])
        : "r"(a[0]), "r"(a[1]), "r"(a[2]), "r"(a[3]),
          "r"(b[0]), "r"(b[1]),
          "f"(c[0]), "f"(c[1]), "f"(c[2]), "f"(c[3]));
}
// fp16 m16n8k16, fp32 accumulate (GEMMs)
__device__ __forceinline__ void mma16(float d[4], const uint32_t a[4],
                                      uint32_t b0, uint32_t b1) {
    asm volatile(
        "mma.sync.aligned.m16n8k16.row.col.f32.f16.f16.f32 "
        "{%0,%1,%2,%3}, {%4,%5,%6,%7}, {%8,%9}, {%0,%1,%2,%3};"
        : "+f"(d[0]), "+f"(d[1]), "+f"(d[2]), "+f"(d[3])
        : "r"(a[0]), "r"(a[1]), "r"(a[2]), "r"(a[3]), "r"(b0), "r"(b1));
}
__device__ __forceinline__ uint32_t smem_u32(const void* p) {
    return (uint32_t)__cvta_generic_to_shared(p);
}

#define CPA16(s, gp) \
    asm volatile("cp.async.cg.shared.global [%0], [%1], 16;" :: "r"(s), "l"(gp))

// ---------------------------------------------------------------------------
// Prepasses: fp32 -> fp16
// ---------------------------------------------------------------------------
__global__ void x_to_half(const float* __restrict__ src, int n4) {
    const int i = blockIdx.x * blockDim.x + threadIdx.x;
    if (i < n4) {
        float4 v = ((const float4*)src)[i];
        __half2* dst = (__half2*)g_xh;
        dst[2 * i]     = __floats2half2_rn(v.x, v.y);
        dst[2 * i + 1] = __floats2half2_rn(v.z, v.w);
    }
}

// transpose + convert: src fp32 [K=1024][ND] -> dst fp16 [ND][1024]
template <int WHICH>
__global__ void transpose_half(const float* __restrict__ src) {
    constexpr int ND = WHICH ? Cn : C3;
    __half* dst = WHICH ? g_wprojT : g_wqkvT;
    __shared__ float t[32][33];
    const int n0 = blockIdx.x * 32, k0 = blockIdx.y * 32;
    const int tx = threadIdx.x, ty = threadIdx.y;
#pragma unroll
    for (int i = 0; i < 4; i++)
        t[ty + 8 * i][tx] = src[(size_t)(k0 + ty + 8 * i) * ND + n0 + tx];
    __syncthreads();
#pragma unroll
    for (int i = 0; i < 4; i++)
        dst[(size_t)(n0 + ty + 8 * i) * Cn + k0 + tx] =
            __float2half_rn(t[tx][ty + 8 * i]);
}

// ---------------------------------------------------------------------------
// fp16 GEMM: out[M,N] = A[M,K] @ W^T[N,K] + bias.  R9 schedule: BM=BN=128,
// BK=16, 8 warps 4x2, warp tile 32x64, double-buffered cp.async.
// m16n8k16 fragments: A [m][k] halves stride 40 (word 20r+q — R9-proven
// conflict-free); B [n][k] halves stride 24 (word 12n+q — all 32 banks
// distinct). One k16 step per tile: 24 LDS + 16 MMA (vs 48+32 for tf32).
// MODE 0: A=g_xh, W=g_wqkvT, scatter raw fp32 -> g_q/g_k/g_v.
// MODE 1: A=g_yh, W=g_wprojT, out + bias.
// ---------------------------------------------------------------------------
#define ABUF 10240              // 128 rows * 80 B
#define BBUF 6144               // 128 rows * 48 B
#define GEMM_SMEM (2 * (ABUF + BBUF))

template <int MODE>
__global__ __launch_bounds__(256, 2) void gemm_h(const float* __restrict__ bias,
                                                 float* __restrict__ out) {
    const __half* __restrict__ A = MODE ? (const __half*)g_yh : (const __half*)g_xh;
    const __half* __restrict__ W = MODE ? (const __half*)g_wprojT : (const __half*)g_wqkvT;

    extern __shared__ char smc[];

    const int tid = threadIdx.x;
    const int lane = tid & 31;
    const int warp = tid >> 5;
    const int warpM = warp & 3;
    const int warpN = warp >> 2;
    const int g = lane >> 2;
    const int q = lane & 3;

    const int rowBase = blockIdx.y * 128;
    const int colBase = blockIdx.x * 128;

    // loaders: row = tid>>1 (0..127), 8-half chunk (tid&1)
    const int lRow = tid >> 1;
    const int lSel = tid & 1;
    const __half* agp = A + (size_t)(rowBase + lRow) * Cn + lSel * 8;
    const __half* bgp = W + (size_t)(colBase + lRow) * Cn + lSel * 8;
    const uint32_t asB = smem_u32(smc) + lRow * 80 + lSel * 16;
    const uint32_t bsB = smem_u32(smc) + 2 * ABUF + lRow * 48 + lSel * 16;

    float acc[2][8][4] = {};

#define ISSUE_TILE(k0, buf)                                       \
    do {                                                          \
        CPA16(asB + (buf) * ABUF, agp + (k0));                    \
        CPA16(bsB + (buf) * BBUF, bgp + (k0));                    \
        asm volatile("cp.async.commit_group;");                   \
    } while (0)

    ISSUE_TILE(0, 0);

    for (int it = 0; it < 64; it++) {
        const int buf = it & 1;
        if (it < 63) {
            ISSUE_TILE((it + 1) * 16, buf ^ 1);
            asm volatile("cp.async.wait_group 1;");
        } else {
            asm volatile("cp.async.wait_group 0;");
        }
        __syncthreads();

        const uint32_t* Aw = (const uint32_t*)(smc + buf * ABUF);
        const uint32_t* Bw = (const uint32_t*)(smc + 2 * ABUF + buf * BBUF);

        uint32_t af[2][4];
#pragma unroll
        for (int mt = 0; mt < 2; mt++) {
            const int r = warpM * 32 + mt * 16 + g;
            af[mt][0] = Aw[r * 20 + q];
            af[mt][1] = Aw[(r + 8) * 20 + q];
            af[mt][2] = Aw[r * 20 + q + 4];
            af[mt][3] = Aw[(r + 8) * 20 + q + 4];
        }
#pragma unroll
        for (int nt = 0; nt < 8; nt++) {
            const int n = warpN * 64 + nt * 8 + g;
            const uint32_t b0 = Bw[n * 12 + q];
            const uint32_t b1 = Bw[n * 12 + q + 4];
#pragma unroll
            for (int mt = 0; mt < 2; mt++)
                mma16(acc[mt][nt], af[mt], b0, b1);
        }
        __syncthreads();
    }

    // Epilogue (C-frag layout identical to tf32 path)
#pragma unroll
    for (int mt = 0; mt < 2; mt++) {
#pragma unroll
        for (int ih = 0; ih < 2; ih++) {
            const int m = rowBase + warpM * 32 + mt * 16 + g + ih * 8;
#pragma unroll
            for (int nt = 0; nt < 8; nt++) {
                const int n = colBase + warpN * 64 + nt * 8 + q * 2;
                const float v0 = acc[mt][nt][ih * 2 + 0] + bias[n];
                const float v1 = acc[mt][nt][ih * 2 + 1] + bias[n + 1];
                if (MODE == 1) {
                    *(float2*)&out[(size_t)m * Cn + n] = make_float2(v0, v1);
                } else {
                    const int which = n >> 10;       // 0=q 1=k 2=v
                    const int cc = n & 1023;
                    const int h = cc >> 6;
                    const int d = cc & 63;
                    const int b = m >> 11;
                    const int t = m & 2047;
                    float* dst = (which == 0) ? g_q : (which == 1) ? g_k : g_v;
                    *(float2*)&dst[(((size_t)b * Hn + h) * Tn + t) * Dn + d] =
                        make_float2(v0, v1);
                }
            }
        }
    }
#undef ISSUE_TILE
}

// ---------------------------------------------------------------------------
// Flash attention — R9 champion verbatim (tf32 mma, f2tf on load), except the
// epilogue writes fp16 to g_yh (proj's A operand).
// ---------------------------------------------------------------------------
#define LKV 72
#define ATTN_SMEM ((2 * 64 * LKV + 4 * 16 * LKV) * 4)

__global__ __launch_bounds__(128, 3) void attn_tc() {
    extern __shared__ float smf[];
    float* Kn = smf;
    float* Vs = smf + 64 * LKV;
    float* Pw = smf + 2 * 64 * LKV;

    const int qt = blockIdx.x;
    const int bh = blockIdx.y;
    const int b = bh >> 4;
    const int h = bh & 15;

    const int tid = threadIdx.x;
    const int w = tid >> 5;
    const int lane = tid & 31;
    const int g = lane >> 2;
    const int q = lane & 3;

    const float qscale = 0.125f * 1.44269504f;
    const float* qg = g_q + ((size_t)bh * Tn + qt * 64 + w * 16) * Dn;
    uint32_t aQ[8][4];
#pragma unroll
    for (int ks = 0; ks < 8; ks++) {
        aQ[ks][0] = __float_as_uint(f2tf(qg[g * Dn + ks * 8 + q] * qscale));
        aQ[ks][1] = __float_as_uint(f2tf(qg[(g + 8) * Dn + ks * 8 + q] * qscale));
        aQ[ks][2] = __float_as_uint(f2tf(qg[g * Dn + ks * 8 + q + 4] * qscale));
        aQ[ks][3] = __float_as_uint(f2tf(qg[(g + 8) * Dn + ks * 8 + q + 4] * qscale));
    }

    float o[8][4] = {};
    float mrow[2] = {-INFINITY, -INFINITY};
    float lrow[2] = {0.0f, 0.0f};

    const float* kg0 = g_k + (size_t)bh * Tn * Dn;
    const float* vg0 = g_v + (size_t)bh * Tn * Dn;
    float* Pme = Pw + w * 16 * LKV;

    for (int j = 0; j <= qt; j++) {
        __syncthreads();
        const float* kg = kg0 + (size_t)j * 64 * Dn;
        const float* vg = vg0 + (size_t)j * 64 * Dn;
        for (int i = tid; i < 64 * 16; i += 128) {
            const int r = i >> 4;
            const int c = (i & 15) * 4;
            float4 k4 = *(const float4*)&kg[r * Dn + c];
            *(float4*)&Kn[r * LKV + c] =
                make_float4(f2tf(k4.x), f2tf(k4.y), f2tf(k4.z), f2tf(k4.w));
            float4 v4 = *(const float4*)&vg[r * Dn + c];
            *(float4*)&Vs[r * LKV + c] =
                make_float4(f2tf(v4.x), f2tf(v4.y), f2tf(v4.z), f2tf(v4.w));
        }
        __syncthreads();

        float s[8][4] = {};
#pragma unroll
        for (int ks = 0; ks < 8; ks++) {
            uint32_t bf[8][2];
#pragma unroll
            for (int nt = 0; nt < 8; nt++) {
                bf[nt][0] = __float_as_uint(Kn[(nt * 8 + g) * LKV + ks * 8 + q]);
                bf[nt][1] = __float_as_uint(Kn[(nt * 8 + g) * LKV + ks * 8 + q + 4]);
            }
#pragma unroll
            for (int nt = 0; nt < 8; nt++)
                mma8(s[nt], aQ[ks], bf[nt], s[nt]);
        }

        if (j == qt) {
            const int lr0 = w * 16 + g;
            const int lr1 = lr0 + 8;
#pragma unroll
            for (int nt = 0; nt < 8; nt++) {
                const int lc = nt * 8 + 2 * q;
                if (lc > lr0) s[nt][0] = -INFINITY;
                if (lc + 1 > lr0) s[nt][1] = -INFINITY;
                if (lc > lr1) s[nt][2] = -INFINITY;
                if (lc + 1 > lr1) s[nt][3] = -INFINITY;
            }
        }

#pragma unroll
        for (int r = 0; r < 2; r++) {
            float mx = mrow[r];
#pragma unroll
            for (int nt = 0; nt < 8; nt++)
                mx = fmaxf(mx, fmaxf(s[nt][2 * r], s[nt][2 * r + 1]));
            mx = fmaxf(mx, __shfl_xor_sync(0xffffffffu, mx, 1));
            mx = fmaxf(mx, __shfl_xor_sync(0xffffffffu, mx, 2));
            const float alpha = ex2(mrow[r] - mx);
            float sum = 0.0f;
#pragma unroll
            for (int nt = 0; nt < 8; nt++) {
                const float p0 = ex2(s[nt][2 * r] - mx);
                const float p1 = ex2(s[nt][2 * r + 1] - mx);
                s[nt][2 * r] = p0;
                s[nt][2 * r + 1] = p1;
                sum += p0 + p1;
                o[nt][2 * r] *= alpha;
                o[nt][2 * r + 1] *= alpha;
            }
            sum += __shfl_xor_sync(0xffffffffu, sum, 1);
            sum += __shfl_xor_sync(0xffffffffu, sum, 2);
            lrow[r] = lrow[r] * alpha + sum;
            mrow[r] = mx;
        }

#pragma unroll
        for (int nt = 0; nt < 8; nt++) {
            *(float2*)&Pme[g * LKV + nt * 8 + 2 * q] =
                make_float2(f2tf(s[nt][0]), f2tf(s[nt][1]));
            *(float2*)&Pme[(g + 8) * LKV + nt * 8 + 2 * q] =
                make_float2(f2tf(s[nt][2]), f2tf(s[nt][3]));
        }
        __syncwarp();

#pragma unroll
        for (int ks = 0; ks < 8; ks++) {
            uint32_t aP[4];
            aP[0] = __float_as_uint(Pme[g * LKV + ks * 8 + q]);
            aP[1] = __float_as_uint(Pme[(g + 8) * LKV + ks * 8 + q]);
            aP[2] = __float_as_uint(Pme[g * LKV + ks * 8 + q + 4]);
            aP[3] = __float_as_uint(Pme[(g + 8) * LKV + ks * 8 + q + 4]);
            uint32_t bf[8][2];
#pragma unroll
            for (int nt = 0; nt < 8; nt++) {
                bf[nt][0] = __float_as_uint(Vs[(ks * 8 + q) * LKV + nt * 8 + g]);
                bf[nt][1] = __float_as_uint(Vs[(ks * 8 + q + 4) * LKV + nt * 8 + g]);
            }
#pragma unroll
            for (int nt = 0; nt < 8; nt++)
                mma8(o[nt], aP, bf[nt], o[nt]);
        }
    }

    // Normalize + write g_yh as fp16 (proj A operand)
    const float inv0 = 1.0f / lrow[0];
    const float inv1 = 1.0f / lrow[1];
    __half* yg = g_yh + ((size_t)b * Tn + qt * 64 + w * 16) * Cn + h * Dn;
#pragma unroll
    for (int nt = 0; nt < 8; nt++) {
        *(__half2*)&yg[(size_t)g * Cn + nt * 8 + 2 * q] =
            __floats2half2_rn(o[nt][0] * inv0, o[nt][1] * inv0);
        *(__half2*)&yg[(size_t)(g + 8) * Cn + nt * 8 + 2 * q] =
            __floats2half2_rn(o[nt][2] * inv1, o[nt][3] * inv1);
    }
}

// ---------------------------------------------------------------------------
extern "C" void kernel_launch(void* const* d_in, const int* in_sizes, int n_in,
                              void* d_out, int out_size) {
    const float* x      = (const float*)d_in[0];
    const float* w_qkv  = (const float*)d_in[1];
    const float* b_qkv  = (const float*)d_in[2];
    const float* w_proj = (const float*)d_in[3];
    const float* b_proj = (const float*)d_in[4];
    float* out = (float*)d_out;

    cudaFuncSetAttribute(attn_tc,
                         cudaFuncAttributeMaxDynamicSharedMemorySize, ATTN_SMEM);
    cudaFuncSetAttribute(gemm_h<0>,
                         cudaFuncAttributeMaxDynamicSharedMemorySize, GEMM_SMEM);
    cudaFuncSetAttribute(gemm_h<1>,
                         cudaFuncAttributeMaxDynamicSharedMemorySize, GEMM_SMEM);

    const int nx4 = NT * Cn / 4;
    x_to_half<<<(nx4 + 255) / 256, 256>>>(x, nx4);
    transpose_half<0><<<dim3(C3 / 32, Cn / 32), dim3(32, 8)>>>(w_qkv);
    transpose_half<1><<<dim3(Cn / 32, Cn / 32), dim3(32, 8)>>>(w_proj);

    gemm_h<0><<<dim3(C3 / 128, NT / 128), 256, GEMM_SMEM>>>(b_qkv, nullptr);
    attn_tc<<<dim3(Tn / 64, Bn * Hn), 128, ATTN_SMEM>>>();
    gemm_h<1><<<dim3(Cn / 128, NT / 128), 256, GEMM_SMEM>>>(b_proj, out);
}